// round 14
// baseline (speedup 1.0000x reference)
#include <cuda_runtime.h>

#define BUF 4194304u
__device__ float g_scratch[5u * BUF];

// ================= common helpers =================
__device__ __forceinline__ unsigned f2tf(float f) {
    unsigned u; asm("cvt.rna.tf32.f32 %0, %1;" : "=r"(u) : "f"(f)); return u;
}
__device__ __forceinline__ float f2tf_f(float f) { return __uint_as_float(f2tf(f)); }
__device__ __forceinline__ unsigned ldu(const float* p) { return __float_as_uint(*p); }
__device__ __forceinline__ void mma_tf32(float& c0, float& c1, float& c2, float& c3,
                                         unsigned a0, unsigned a1, unsigned a2, unsigned a3,
                                         unsigned b0, unsigned b1) {
    asm volatile("mma.sync.aligned.m16n8k8.row.col.f32.tf32.tf32.f32 "
                 "{%0,%1,%2,%3}, {%4,%5,%6,%7}, {%8,%9}, {%0,%1,%2,%3};"
                 : "+f"(c0), "+f"(c1), "+f"(c2), "+f"(c3)
                 : "r"(a0), "r"(a1), "r"(a2), "r"(a3), "r"(b0), "r"(b1));
}
#define CP_COMMIT()  asm volatile("cp.async.commit_group;" ::: "memory")
#define CP_WAIT(N)   asm volatile("cp.async.wait_group %0;" :: "n"(N) : "memory")
__device__ __forceinline__ void cp16(unsigned dst, const float* src) {
    asm volatile("cp.async.cg.shared.global [%0], [%1], 16;" :: "r"(dst), "l"(src));
}
#define BARS(ID, CNT) asm volatile("bar.sync %0, %1;" :: "r"(ID), "r"(CNT) : "memory")
#define BARA(ID, CNT) asm volatile("bar.arrive %0, %1;" :: "r"(ID), "r"(CNT) : "memory")

// ================= tf32 tensor GEMM (M=4096,N=1024,K=1024) =================
#define GA0 0
#define GA1 4096
#define GB0 8192
#define GB1 12544
#define GSM_BYTES ((12544 + 4352) * 4)

template <int SPLIT, int ROUND>
__device__ __forceinline__ void gemm_body(const float* __restrict__ A,
                                          const float* __restrict__ B,
                                          const float* __restrict__ R,
                                          float* __restrict__ C,
                                          float* smg, unsigned smb) {
    const int t = threadIdx.x;
    const int n0 = blockIdx.x * 128, m0 = blockIdx.y * 128;
    const int lane = t & 31, w = t >> 5, g = lane >> 2, tig = lane & 3;
    const int m0w = (w >> 2) * 64, n0w = (w & 3) * 32;

    float acc[4][4][4];
#pragma unroll
    for (int mf = 0; mf < 4; mf++)
#pragma unroll
        for (int nf = 0; nf < 4; nf++)
#pragma unroll
            for (int r = 0; r < 4; r++) acc[mf][nf][r] = 0.f;

    auto stage = [&](int kc, int buf) {
        const float* Ab = A + (size_t)m0 * 1024 + kc * 32;
        const unsigned abase = smb + (buf ? GA1 * 4u : 0u);
#pragma unroll
        for (int i = 0; i < 4; i++) {
            const int gi = i * 256 + t;
            const int m = gi >> 3, kq = gi & 7;
            cp16(abase + (unsigned)(m * 32 + 4 * (kq ^ (m & 7))) * 4u,
                 Ab + (size_t)m * 1024 + kq * 4);
        }
        const float* Bb = B + (size_t)kc * 32 * 1024 + n0;
        const unsigned bbase = smb + (unsigned)(buf ? GB1 : GB0) * 4u;
#pragma unroll
        for (int i = 0; i < 4; i++) {
            const int gi = i * 256 + t;
            const int k = gi >> 5, nq = gi & 31;
            cp16(bbase + (unsigned)(k * 136 + nq * 4) * 4u,
                 Bb + (size_t)k * 1024 + nq * 4);
        }
    };

    stage(0, 0);
    CP_COMMIT();

    for (int kc = 0; kc < 32; kc++) {
        stage(kc + 1 < 32 ? kc + 1 : 31, (kc + 1) & 1);
        CP_COMMIT();
        CP_WAIT(1);
        __syncthreads();
        const float* Asb = smg + ((kc & 1) ? GA1 : GA0);
        const float* Bsb = smg + ((kc & 1) ? GB1 : GB0);
#pragma unroll
        for (int ks = 0; ks < 4; ks++) {
            unsigned bh[4][2], bl[4][2];
#pragma unroll
            for (int nf = 0; nf < 4; nf++) {
                const float* bp = Bsb + (ks * 8 + tig) * 136 + n0w + nf * 8 + g;
                float b0 = bp[0], b1 = bp[4 * 136];
                bh[nf][0] = f2tf(b0);
                bh[nf][1] = f2tf(b1);
                if (SPLIT == 3) {
                    bl[nf][0] = f2tf(b0 - __uint_as_float(bh[nf][0]));
                    bl[nf][1] = f2tf(b1 - __uint_as_float(bh[nf][1]));
                }
            }
#pragma unroll
            for (int mf = 0; mf < 4; mf++) {
                const float* ap  = Asb + (m0w + mf * 16 + g) * 32;
                const float* ap8 = ap + 8 * 32;
                const int q0 = 4 * ((2 * ks) ^ g), q1 = 4 * ((2 * ks + 1) ^ g);
                float a0 = ap[q0 + tig], a1 = ap8[q0 + tig];
                float a2 = ap[q1 + tig], a3 = ap8[q1 + tig];
                unsigned h0 = f2tf(a0), h1 = f2tf(a1), h2 = f2tf(a2), h3 = f2tf(a3);
                unsigned l0 = 0, l1 = 0, l2 = 0, l3 = 0;
                if (SPLIT == 3) {
                    l0 = f2tf(a0 - __uint_as_float(h0));
                    l1 = f2tf(a1 - __uint_as_float(h1));
                    l2 = f2tf(a2 - __uint_as_float(h2));
                    l3 = f2tf(a3 - __uint_as_float(h3));
                }
#pragma unroll
                for (int nf = 0; nf < 4; nf++) {
                    mma_tf32(acc[mf][nf][0], acc[mf][nf][1], acc[mf][nf][2], acc[mf][nf][3],
                             h0, h1, h2, h3, bh[nf][0], bh[nf][1]);
                    if (SPLIT == 3) {
                        mma_tf32(acc[mf][nf][0], acc[mf][nf][1], acc[mf][nf][2], acc[mf][nf][3],
                                 h0, h1, h2, h3, bl[nf][0], bl[nf][1]);
                        mma_tf32(acc[mf][nf][0], acc[mf][nf][1], acc[mf][nf][2], acc[mf][nf][3],
                                 l0, l1, l2, l3, bh[nf][0], bh[nf][1]);
                    }
                }
            }
        }
        __syncthreads();
    }

#pragma unroll
    for (int mf = 0; mf < 4; mf++)
#pragma unroll
        for (int nf = 0; nf < 4; nf++) {
            const int r0 = m0 + m0w + mf * 16 + g;
            const int col = n0 + n0w + nf * 8 + 2 * tig;
            float2 v0 = make_float2(acc[mf][nf][0], acc[mf][nf][1]);
            float2 v1 = make_float2(acc[mf][nf][2], acc[mf][nf][3]);
            if (R) {
                float2 r0v = *(const float2*)&R[(size_t)r0 * 1024 + col];
                float2 r1v = *(const float2*)&R[(size_t)(r0 + 8) * 1024 + col];
                v0.x += r0v.x; v0.y += r0v.y;
                v1.x += r1v.x; v1.y += r1v.y;
            }
            if (ROUND) {
                v0.x = f2tf_f(v0.x); v0.y = f2tf_f(v0.y);
                v1.x = f2tf_f(v1.x); v1.y = f2tf_f(v1.y);
            }
            *(float2*)&C[(size_t)r0 * 1024 + col] = v0;
            *(float2*)&C[(size_t)(r0 + 8) * 1024 + col] = v1;
        }
}

__global__ __launch_bounds__(256, 2)
void qkv_gemm(const float* __restrict__ iQ, const float* __restrict__ iK,
              const float* __restrict__ iV, const float* __restrict__ WQ,
              const float* __restrict__ WK, const float* __restrict__ WV,
              float* __restrict__ Qo, float* __restrict__ Ko, float* __restrict__ Vo) {
    extern __shared__ float smg[];
    unsigned smb;
    asm("{ .reg .u64 a; cvta.to.shared.u64 a, %1; cvt.u32.u64 %0, a; }"
        : "=r"(smb) : "l"(smg));
    if (blockIdx.z == 0)      gemm_body<1, 1>(iQ, WQ, nullptr, Qo, smg, smb);
    else if (blockIdx.z == 1) gemm_body<1, 1>(iK, WK, nullptr, Ko, smg, smb);
    else                      gemm_body<1, 1>(iV, WV, nullptr, Vo, smg, smb);
}

__global__ __launch_bounds__(256, 2)
void o_gemm(const float* __restrict__ A, const float* __restrict__ B,
            const float* __restrict__ R, float* __restrict__ C) {
    extern __shared__ float smg[];
    unsigned smb;
    asm("{ .reg .u64 a; cvta.to.shared.u64 a, %1; cvt.u32.u64 %0, a; }"
        : "=r"(smb) : "l"(smg));
    gemm_body<1, 0>(A, B, R, C, smg, smb);
}

// ================= warp-specialized attention, softmax over HEADS ============
// Producers (warps 0-7): scores via smem-staged K. Consumers (warps 8-15):
// softmax + context with V read DIRECTLY from L2 into registers (no smem V).
#define K0O 0
#define K1O 8704
#define SSB 17408           // SS[p] = SSB + p*2192, entry sc[q*137+k*17+h]
#define SM_FLOATS (17408 + 2 * 2192)
#define SM_BYTES (SM_FLOATS * 4)

__device__ __forceinline__ void stage16(const float* __restrict__ src,
                                        unsigned dst_u32, int t) {
#pragma unroll
    for (int i = 0; i < 8; i++) {
        const int f = i * 512 + t;
        const int r = f >> 8;
        const int c = f & 255;
        const int row = ((c >> 4) << 4) + r;
        cp16(dst_u32 + (unsigned)(row * 68 + (c & 15) * 4) * 4u,
             src + (size_t)r * 1024 + c * 4);
    }
}
__device__ __forceinline__ void stage8h(const float* __restrict__ src,
                                        unsigned dst_u32, int tc) {
#pragma unroll
    for (int i = 0; i < 8; i++) {
        const int f = i * 256 + tc;
        const int r = f >> 8;
        const int c = f & 255;
        const int row = ((c >> 4) << 3) + r;
        cp16(dst_u32 + (unsigned)(row * 68 + (c & 15) * 4) * 4u,
             src + (size_t)r * 1024 + c * 4);
    }
}

__global__ __launch_bounds__(512, 1)
void attn_kernel(const float* __restrict__ Q, const float* __restrict__ K,
                 const float* __restrict__ V, float* __restrict__ Ctx) {
    extern __shared__ float sm[];
    unsigned smb;
    asm("{ .reg .u64 a; cvta.to.shared.u64 a, %1; cvt.u32.u64 %0, a; }"
        : "=r"(smb) : "l"(sm));

    const int t = threadIdx.x;
    const int b = blockIdx.y;
    const int q0g = blockIdx.x << 4;
    const int kt0 = blockIdx.z * 64;

    const float* Qb = Q + ((size_t)b * 2048 + q0g) * 1024;
    const float* Kb = K + (size_t)b * 2048 * 1024;
    const float* Vb = V + (size_t)b * 2048 * 1024;

    const int w    = t >> 5;
    const int lane = t & 31;
    const int g    = lane >> 2;
    const int tig  = lane & 3;

    stage16(Qb, smb, t);
    CP_COMMIT();
    CP_WAIT(0);
    __syncthreads();

    if (t < 256) {
        // ======================= PRODUCERS =======================
        unsigned aq[2][8][4];
#pragma unroll
        for (int i = 0; i < 2; i++) {
            const int head = 2 * w + i;
            const float* qp = &sm[(head * 16 + g) * 68];
#pragma unroll
            for (int ks = 0; ks < 8; ks++) {
                aq[i][ks][0] = ldu(qp + ks * 8 + tig);
                aq[i][ks][1] = ldu(qp + 8 * 68 + ks * 8 + tig);
                aq[i][ks][2] = ldu(qp + ks * 8 + tig + 4);
                aq[i][ks][3] = ldu(qp + 8 * 68 + ks * 8 + tig + 4);
            }
        }
        __syncthreads();

        stage8h(Kb + (size_t)kt0 * 8 * 1024, smb + K0O * 4u, t);
        CP_COMMIT();
        stage8h(Kb + (size_t)(kt0 + 1) * 8 * 1024, smb + K1O * 4u, t);
        CP_COMMIT();

        for (int j = 0; j < 64; j++) {
            const int p = j & 1;
            if (j >= 2) BARS(3 + p, 512);
            CP_WAIT(1);
            BARS(5, 256);

            float* SSc = sm + SSB + p * 2192;
            const float* kbase = sm + (p ? K1O : K0O);
#pragma unroll
            for (int i = 0; i < 2; i++) {
                const int head = 2 * w + i;
                const float* kp = kbase + (head * 8 + g) * 68;
                float c0a = 0.f, c1a = 0.f, c2a = 0.f, c3a = 0.f;
                float c0b = 0.f, c1b = 0.f, c2b = 0.f, c3b = 0.f;
#pragma unroll
                for (int ks = 0; ks < 4; ks++) {
                    unsigned b0 = ldu(kp + ks * 8 + tig);
                    unsigned b1 = ldu(kp + ks * 8 + tig + 4);
                    mma_tf32(c0a, c1a, c2a, c3a,
                             aq[i][ks][0], aq[i][ks][1], aq[i][ks][2], aq[i][ks][3], b0, b1);
                }
#pragma unroll
                for (int ks = 4; ks < 8; ks++) {
                    unsigned b0 = ldu(kp + ks * 8 + tig);
                    unsigned b1 = ldu(kp + ks * 8 + tig + 4);
                    mma_tf32(c0b, c1b, c2b, c3b,
                             aq[i][ks][0], aq[i][ks][1], aq[i][ks][2], aq[i][ks][3], b0, b1);
                }
                float* sp = SSc + g * 137 + 2 * tig * 17 + head;
                sp[0]            = (c0a + c0b) * 0.125f;
                sp[17]           = (c1a + c1b) * 0.125f;
                sp[8 * 137]      = (c2a + c2b) * 0.125f;
                sp[8 * 137 + 17] = (c3a + c3b) * 0.125f;
            }
            BARA(1 + p, 512);
            BARS(5, 256);
            {
                const int jn = (j + 2 < 64) ? j + 2 : 63;
                stage8h(Kb + (size_t)(kt0 + jn) * 8 * 1024,
                        smb + (unsigned)(p ? K1O : K0O) * 4u, t);
                CP_COMMIT();
            }
        }
    } else {
        // ======================= CONSUMERS =======================
        const int tc = t - 256;
        const int wc = w - 8;
        __syncthreads();

        float cacc[2][8][4];
#pragma unroll
        for (int i = 0; i < 2; i++)
#pragma unroll
            for (int n = 0; n < 8; n++)
#pragma unroll
                for (int r = 0; r < 4; r++) cacc[i][n][r] = 0.f;

        const int sxq = (tc >> 1) >> 3, sxk = (tc >> 1) & 7, half = tc & 1;

        for (int j = 0; j < 64; j++) {
            const int p = j & 1;
            BARS(1 + p, 512);      // scores(j) ready; all consumers past context(j-1)

            // ---- V(j) direct from L2 into registers (latency hidden by softmax) ----
            float vreg[2][8][2];
            {
                const float* vr0 = Vb + (size_t)(kt0 + j) * 8 * 1024 + (size_t)tig * 1024 + g;
                const float* vr1 = vr0 + 4 * 1024;
#pragma unroll
                for (int i = 0; i < 2; i++) {
                    const int hoff = (2 * wc + i) * 64;
#pragma unroll
                    for (int nt = 0; nt < 8; nt++) {
                        vreg[i][nt][0] = __ldg(vr0 + hoff + nt * 8);
                        vreg[i][nt][1] = __ldg(vr1 + hoff + nt * 8);
                    }
                }
            }

            float* SSc = sm + SSB + p * 2192;
            // ---- softmax over 16 heads ----
            {
                float* pp = SSc + sxq * 137 + sxk * 17 + 8 * half;
                float e0 = __expf(pp[0]), e1 = __expf(pp[1]);
                float e2 = __expf(pp[2]), e3 = __expf(pp[3]);
                float e4 = __expf(pp[4]), e5 = __expf(pp[5]);
                float e6 = __expf(pp[6]), e7 = __expf(pp[7]);
                float s = ((e0 + e1) + (e2 + e3)) + ((e4 + e5) + (e6 + e7));
                s += __shfl_xor_sync(0xffffffffu, s, 1);
                const float inv = __frcp_rn(s);
                pp[0] = e0 * inv; pp[1] = e1 * inv; pp[2] = e2 * inv; pp[3] = e3 * inv;
                pp[4] = e4 * inv; pp[5] = e5 * inv; pp[6] = e6 * inv; pp[7] = e7 * inv;
            }
            BARS(6, 256);          // softmax visible among consumers

            // ---- context for 2 heads (V from registers) ----
#pragma unroll
            for (int i = 0; i < 2; i++) {
                const int head = 2 * wc + i;
                unsigned a0 = f2tf(SSc[g * 137 + tig * 17 + head]);
                unsigned a1 = f2tf(SSc[(g + 8) * 137 + tig * 17 + head]);
                unsigned a2 = f2tf(SSc[g * 137 + (tig + 4) * 17 + head]);
                unsigned a3 = f2tf(SSc[(g + 8) * 137 + (tig + 4) * 17 + head]);
#pragma unroll
                for (int nt = 0; nt < 8; nt++) {
                    mma_tf32(cacc[i][nt][0], cacc[i][nt][1], cacc[i][nt][2], cacc[i][nt][3],
                             a0, a1, a2, a3,
                             __float_as_uint(vreg[i][nt][0]),
                             __float_as_uint(vreg[i][nt][1]));
                }
            }
            if (j < 63) BARA(3 + p, 512);
        }

#pragma unroll
        for (int i = 0; i < 2; i++) {
            const int head = 2 * wc + i;
#pragma unroll
            for (int nt = 0; nt < 8; nt++) {
                const size_t base = ((size_t)b * 2048 + q0g + g) * 1024
                                  + head * 64 + nt * 8 + 2 * tig;
                atomicAdd(&Ctx[base + 0], cacc[i][nt][0]);
                atomicAdd(&Ctx[base + 1], cacc[i][nt][1]);
                atomicAdd(&Ctx[base + 8 * 1024 + 0], cacc[i][nt][2]);
                atomicAdd(&Ctx[base + 8 * 1024 + 1], cacc[i][nt][3]);
            }
        }
    }
}

// ================= LayerNorm over last dim (1024) =================
__global__ __launch_bounds__(256)
void ln_kernel(const float* __restrict__ x, const float* __restrict__ gamma,
               const float* __restrict__ beta, float* __restrict__ out) {
    __shared__ float red[16];
    const int row = blockIdx.x, t = threadIdx.x;
    float4 v = ((const float4*)(x + (size_t)row * 1024))[t];
    float s = v.x + v.y + v.z + v.w;
    float q = v.x * v.x + v.y * v.y + v.z * v.z + v.w * v.w;
#pragma unroll
    for (int o = 16; o > 0; o >>= 1) {
        s += __shfl_xor_sync(0xffffffffu, s, o);
        q += __shfl_xor_sync(0xffffffffu, q, o);
    }
    if ((t & 31) == 0) { red[t >> 5] = s; red[8 + (t >> 5)] = q; }
    __syncthreads();
    if (t < 8) {
        s = red[t]; q = red[8 + t];
#pragma unroll
        for (int o = 4; o > 0; o >>= 1) {
            s += __shfl_xor_sync(0xffu, s, o);
            q += __shfl_xor_sync(0xffu, q, o);
        }
        if (t == 0) { red[0] = s; red[1] = q; }
    }
    __syncthreads();
    const float mu = red[0] * (1.f / 1024.f);
    const float var = red[1] * (1.f / 1024.f) - mu * mu;
    const float inv = rsqrtf(var + 1e-5f);
    float4 g = ((const float4*)gamma)[t];
    float4 bb = ((const float4*)beta)[t];
    float4 o;
    o.x = (v.x - mu) * inv * g.x + bb.x;
    o.y = (v.y - mu) * inv * g.y + bb.y;
    o.z = (v.z - mu) * inv * g.z + bb.z;
    o.w = (v.w - mu) * inv * g.w + bb.w;
    ((float4*)(out + (size_t)row * 1024))[t] = o;
}

// ================= launch =================
extern "C" void kernel_launch(void* const* d_in, const int* in_sizes, int n_in,
                              void* d_out, int out_size) {
    const float* inQ = (const float*)d_in[0];
    const float* inK = (const float*)d_in[1];
    const float* inV = (const float*)d_in[2];
    const float* WQ  = (const float*)d_in[3];
    const float* WK  = (const float*)d_in[4];
    const float* WV  = (const float*)d_in[5];
    const float* WO  = (const float*)d_in[6];
    const float* gam = (const float*)d_in[7];
    const float* bet = (const float*)d_in[8];
    float* out = (float*)d_out;

    float* base = nullptr;
    cudaGetSymbolAddress((void**)&base, g_scratch);
    float* Qb = base;
    float* Kb = base + BUF;
    float* Vb = base + 2 * BUF;
    float* Cx = base + 3 * BUF;
    float* Xb = base + 4 * BUF;

    cudaFuncSetAttribute(qkv_gemm, cudaFuncAttributeMaxDynamicSharedMemorySize, GSM_BYTES);
    cudaFuncSetAttribute(o_gemm, cudaFuncAttributeMaxDynamicSharedMemorySize, GSM_BYTES);

    qkv_gemm<<<dim3(8, 32, 3), 256, GSM_BYTES>>>(inQ, inK, inV, WQ, WK, WV, Qb, Kb, Vb);

    cudaMemsetAsync(Cx, 0, BUF * sizeof(float));

    cudaFuncSetAttribute(attn_kernel, cudaFuncAttributeMaxDynamicSharedMemorySize, SM_BYTES);
    attn_kernel<<<dim3(128, 2, 4), 512, SM_BYTES>>>(Qb, Kb, Vb, Cx);

    o_gemm<<<dim3(8, 32), 256, GSM_BYTES>>>(Cx, WO, inQ, Xb);
    ln_kernel<<<4096, 256>>>(Xb, gam, bet, out);
}

// round 16
// speedup vs baseline: 1.1907x; 1.1907x over previous
#include <cuda_runtime.h>

#define BUF 4194304u
__device__ float g_scratch[5u * BUF];

// ================= common helpers =================
__device__ __forceinline__ unsigned f2tf(float f) {
    unsigned u; asm("cvt.rna.tf32.f32 %0, %1;" : "=r"(u) : "f"(f)); return u;
}
__device__ __forceinline__ float f2tf_f(float f) { return __uint_as_float(f2tf(f)); }
__device__ __forceinline__ unsigned ldu(const float* p) { return __float_as_uint(*p); }
__device__ __forceinline__ void mma_tf32(float& c0, float& c1, float& c2, float& c3,
                                         unsigned a0, unsigned a1, unsigned a2, unsigned a3,
                                         unsigned b0, unsigned b1) {
    asm volatile("mma.sync.aligned.m16n8k8.row.col.f32.tf32.tf32.f32 "
                 "{%0,%1,%2,%3}, {%4,%5,%6,%7}, {%8,%9}, {%0,%1,%2,%3};"
                 : "+f"(c0), "+f"(c1), "+f"(c2), "+f"(c3)
                 : "r"(a0), "r"(a1), "r"(a2), "r"(a3), "r"(b0), "r"(b1));
}
#define CP_COMMIT()  asm volatile("cp.async.commit_group;" ::: "memory")
#define CP_WAIT(N)   asm volatile("cp.async.wait_group %0;" :: "n"(N) : "memory")
__device__ __forceinline__ void cp16(unsigned dst, const float* src) {
    asm volatile("cp.async.cg.shared.global [%0], [%1], 16;" :: "r"(dst), "l"(src));
}
#define BARS(ID, CNT) asm volatile("bar.sync %0, %1;" :: "r"(ID), "r"(CNT) : "memory")
#define BARA(ID, CNT) asm volatile("bar.arrive %0, %1;" :: "r"(ID), "r"(CNT) : "memory")

// ================= tf32 tensor GEMM (M=4096,N=1024,K=1024) =================
// Operands RNA-converted to tf32 (unbiased). ROUND=1: RNA-round outputs to
// exact tf32 so the attention-side raw-bit feed is lossless.
#define GA0 0
#define GA1 4096
#define GB0 8192
#define GB1 12544
#define GSM_BYTES ((12544 + 4352) * 4)

template <int ROUND>
__device__ __forceinline__ void gemm_body(const float* __restrict__ A,
                                          const float* __restrict__ B,
                                          const float* __restrict__ R,
                                          float* __restrict__ C,
                                          float* smg, unsigned smb) {
    const int t = threadIdx.x;
    const int n0 = blockIdx.x * 128, m0 = blockIdx.y * 128;
    const int lane = t & 31, g = lane >> 2, tig = lane & 3;
    const int w = t >> 5;
    const int m0w = (w >> 2) * 64, n0w = (w & 3) * 32;

    float acc[4][4][4];
#pragma unroll
    for (int mf = 0; mf < 4; mf++)
#pragma unroll
        for (int nf = 0; nf < 4; nf++)
#pragma unroll
            for (int r = 0; r < 4; r++) acc[mf][nf][r] = 0.f;

    auto stage = [&](int kc, int buf) {
        const float* Ab = A + (size_t)m0 * 1024 + kc * 32;
        const unsigned abase = smb + (buf ? GA1 * 4u : 0u);
#pragma unroll
        for (int i = 0; i < 4; i++) {
            const int gi = i * 256 + t;
            const int m = gi >> 3, kq = gi & 7;
            cp16(abase + (unsigned)(m * 32 + 4 * (kq ^ (m & 7))) * 4u,
                 Ab + (size_t)m * 1024 + kq * 4);
        }
        const float* Bb = B + (size_t)kc * 32 * 1024 + n0;
        const unsigned bbase = smb + (unsigned)(buf ? GB1 : GB0) * 4u;
#pragma unroll
        for (int i = 0; i < 4; i++) {
            const int gi = i * 256 + t;
            const int k = gi >> 5, nq = gi & 31;
            cp16(bbase + (unsigned)(k * 136 + nq * 4) * 4u,
                 Bb + (size_t)k * 1024 + nq * 4);
        }
    };

    stage(0, 0);
    CP_COMMIT();

    for (int kc = 0; kc < 32; kc++) {
        stage(kc + 1 < 32 ? kc + 1 : 31, (kc + 1) & 1);
        CP_COMMIT();
        CP_WAIT(1);
        __syncthreads();
        const float* Asb = smg + ((kc & 1) ? GA1 : GA0);
        const float* Bsb = smg + ((kc & 1) ? GB1 : GB0);
#pragma unroll
        for (int ks = 0; ks < 4; ks++) {
            unsigned bh[4][2];
#pragma unroll
            for (int nf = 0; nf < 4; nf++) {
                const float* bp = Bsb + (ks * 8 + tig) * 136 + n0w + nf * 8 + g;
                bh[nf][0] = f2tf(bp[0]);
                bh[nf][1] = f2tf(bp[4 * 136]);
            }
#pragma unroll
            for (int mf = 0; mf < 4; mf++) {
                const float* ap  = Asb + (m0w + mf * 16 + g) * 32;
                const float* ap8 = ap + 8 * 32;
                const int q0 = 4 * ((2 * ks) ^ g), q1 = 4 * ((2 * ks + 1) ^ g);
                unsigned h0 = f2tf(ap[q0 + tig]);
                unsigned h1 = f2tf(ap8[q0 + tig]);
                unsigned h2 = f2tf(ap[q1 + tig]);
                unsigned h3 = f2tf(ap8[q1 + tig]);
#pragma unroll
                for (int nf = 0; nf < 4; nf++) {
                    mma_tf32(acc[mf][nf][0], acc[mf][nf][1], acc[mf][nf][2], acc[mf][nf][3],
                             h0, h1, h2, h3, bh[nf][0], bh[nf][1]);
                }
            }
        }
        __syncthreads();
    }

#pragma unroll
    for (int mf = 0; mf < 4; mf++)
#pragma unroll
        for (int nf = 0; nf < 4; nf++) {
            const int r0 = m0 + m0w + mf * 16 + g;
            const int col = n0 + n0w + nf * 8 + 2 * tig;
            float2 v0 = make_float2(acc[mf][nf][0], acc[mf][nf][1]);
            float2 v1 = make_float2(acc[mf][nf][2], acc[mf][nf][3]);
            if (R) {
                float2 r0v = *(const float2*)&R[(size_t)r0 * 1024 + col];
                float2 r1v = *(const float2*)&R[(size_t)(r0 + 8) * 1024 + col];
                v0.x += r0v.x; v0.y += r0v.y;
                v1.x += r1v.x; v1.y += r1v.y;
            }
            if (ROUND) {
                v0.x = f2tf_f(v0.x); v0.y = f2tf_f(v0.y);
                v1.x = f2tf_f(v1.x); v1.y = f2tf_f(v1.y);
            }
            *(float2*)&C[(size_t)r0 * 1024 + col] = v0;
            *(float2*)&C[(size_t)(r0 + 8) * 1024 + col] = v1;
        }
}

__global__ __launch_bounds__(256, 2)
void qkv_gemm(const float* __restrict__ iQ, const float* __restrict__ iK,
              const float* __restrict__ iV, const float* __restrict__ WQ,
              const float* __restrict__ WK, const float* __restrict__ WV,
              float* __restrict__ Qo, float* __restrict__ Ko, float* __restrict__ Vo) {
    extern __shared__ float smg[];
    unsigned smb;
    asm("{ .reg .u64 a; cvta.to.shared.u64 a, %1; cvt.u32.u64 %0, a; }"
        : "=r"(smb) : "l"(smg));
    if (blockIdx.z == 0)      gemm_body<1>(iQ, WQ, nullptr, Qo, smg, smb);
    else if (blockIdx.z == 1) gemm_body<1>(iK, WK, nullptr, Ko, smg, smb);
    else                      gemm_body<1>(iV, WV, nullptr, Vo, smg, smb);
}

__global__ __launch_bounds__(256, 2)
void o_gemm(const float* __restrict__ A, const float* __restrict__ B,
            const float* __restrict__ R, float* __restrict__ C) {
    extern __shared__ float smg[];
    unsigned smb;
    asm("{ .reg .u64 a; cvta.to.shared.u64 a, %1; cvt.u32.u64 %0, a; }"
        : "=r"(smb) : "l"(smg));
    gemm_body<0>(A, B, R, C, smg, smb);
}

// ================= warp-specialized attention, softmax over HEADS ============
// R13 winner + consumer reorder: softmax overlaps V arrival; one BARS(6)/tile.
#define K0O 0
#define K1O 8704
#define VBA 17408
#define VBB 26112
#define SSB 34816           // SS[p] = SSB + p*2192, entry sc[q*137+k*17+h]
#define SM_FLOATS (34816 + 2 * 2192)
#define SM_BYTES (SM_FLOATS * 4)

__device__ __forceinline__ void stage16(const float* __restrict__ src,
                                        unsigned dst_u32, int t) {
#pragma unroll
    for (int i = 0; i < 8; i++) {
        const int f = i * 512 + t;
        const int r = f >> 8;
        const int c = f & 255;
        const int row = ((c >> 4) << 4) + r;
        cp16(dst_u32 + (unsigned)(row * 68 + (c & 15) * 4) * 4u,
             src + (size_t)r * 1024 + c * 4);
    }
}
__device__ __forceinline__ void stage8h(const float* __restrict__ src,
                                        unsigned dst_u32, int tc) {
#pragma unroll
    for (int i = 0; i < 8; i++) {
        const int f = i * 256 + tc;
        const int r = f >> 8;
        const int c = f & 255;
        const int row = ((c >> 4) << 3) + r;
        cp16(dst_u32 + (unsigned)(row * 68 + (c & 15) * 4) * 4u,
             src + (size_t)r * 1024 + c * 4);
    }
}

__global__ __launch_bounds__(512, 1)
void attn_kernel(const float* __restrict__ Q, const float* __restrict__ K,
                 const float* __restrict__ V, float* __restrict__ Ctx) {
    extern __shared__ float sm[];
    unsigned smb;
    asm("{ .reg .u64 a; cvta.to.shared.u64 a, %1; cvt.u32.u64 %0, a; }"
        : "=r"(smb) : "l"(sm));

    const int t = threadIdx.x;
    const int b = blockIdx.y;
    const int q0g = blockIdx.x << 4;
    const int kt0 = blockIdx.z * 64;

    const float* Qb = Q + ((size_t)b * 2048 + q0g) * 1024;
    const float* Kb = K + (size_t)b * 2048 * 1024;
    const float* Vb = V + (size_t)b * 2048 * 1024;

    const int w    = t >> 5;
    const int lane = t & 31;
    const int g    = lane >> 2;
    const int tig  = lane & 3;

    stage16(Qb, smb, t);
    CP_COMMIT();
    CP_WAIT(0);
    __syncthreads();

    if (t < 256) {
        // ======================= PRODUCERS =======================
        unsigned aq[2][8][4];
#pragma unroll
        for (int i = 0; i < 2; i++) {
            const int head = 2 * w + i;
            const float* qp = &sm[(head * 16 + g) * 68];
#pragma unroll
            for (int ks = 0; ks < 8; ks++) {
                aq[i][ks][0] = ldu(qp + ks * 8 + tig);
                aq[i][ks][1] = ldu(qp + 8 * 68 + ks * 8 + tig);
                aq[i][ks][2] = ldu(qp + ks * 8 + tig + 4);
                aq[i][ks][3] = ldu(qp + 8 * 68 + ks * 8 + tig + 4);
            }
        }
        __syncthreads();

        stage8h(Kb + (size_t)kt0 * 8 * 1024, smb + K0O * 4u, t);
        CP_COMMIT();
        stage8h(Kb + (size_t)(kt0 + 1) * 8 * 1024, smb + K1O * 4u, t);
        CP_COMMIT();

        for (int j = 0; j < 64; j++) {
            const int p = j & 1;
            if (j >= 2) BARS(3 + p, 512);
            CP_WAIT(1);
            BARS(5, 256);

            float* SSc = sm + SSB + p * 2192;
            const float* kbase = sm + (p ? K1O : K0O);
#pragma unroll
            for (int i = 0; i < 2; i++) {
                const int head = 2 * w + i;
                const float* kp = kbase + (head * 8 + g) * 68;
                float c0a = 0.f, c1a = 0.f, c2a = 0.f, c3a = 0.f;
                float c0b = 0.f, c1b = 0.f, c2b = 0.f, c3b = 0.f;
#pragma unroll
                for (int ks = 0; ks < 4; ks++) {
                    unsigned b0 = ldu(kp + ks * 8 + tig);
                    unsigned b1 = ldu(kp + ks * 8 + tig + 4);
                    mma_tf32(c0a, c1a, c2a, c3a,
                             aq[i][ks][0], aq[i][ks][1], aq[i][ks][2], aq[i][ks][3], b0, b1);
                }
#pragma unroll
                for (int ks = 4; ks < 8; ks++) {
                    unsigned b0 = ldu(kp + ks * 8 + tig);
                    unsigned b1 = ldu(kp + ks * 8 + tig + 4);
                    mma_tf32(c0b, c1b, c2b, c3b,
                             aq[i][ks][0], aq[i][ks][1], aq[i][ks][2], aq[i][ks][3], b0, b1);
                }
                float* sp = SSc + g * 137 + 2 * tig * 17 + head;
                sp[0]            = (c0a + c0b) * 0.125f;
                sp[17]           = (c1a + c1b) * 0.125f;
                sp[8 * 137]      = (c2a + c2b) * 0.125f;
                sp[8 * 137 + 17] = (c3a + c3b) * 0.125f;
            }
            BARA(1 + p, 512);
            BARS(5, 256);
            {
                const int jn = (j + 2 < 64) ? j + 2 : 63;
                stage8h(Kb + (size_t)(kt0 + jn) * 8 * 1024,
                        smb + (unsigned)(p ? K1O : K0O) * 4u, t);
                CP_COMMIT();
            }
        }
    } else {
        // ======================= CONSUMERS =======================
        const int tc = t - 256;
        const int wc = w - 8;
        __syncthreads();

        stage8h(Vb + (size_t)kt0 * 8 * 1024, smb + VBA * 4u, tc);
        CP_COMMIT();

        float cacc[2][8][4];
#pragma unroll
        for (int i = 0; i < 2; i++)
#pragma unroll
            for (int n = 0; n < 8; n++)
#pragma unroll
                for (int r = 0; r < 4; r++) cacc[i][n][r] = 0.f;

        const int sxq = (tc >> 1) >> 3, sxk = (tc >> 1) & 7, half = tc & 1;

        for (int j = 0; j < 64; j++) {
            const int p = j & 1;
            BARS(1 + p, 512);      // scores(j) ready; all consumers past context(j-1)
            {
                const int jn = (j + 1 < 64) ? j + 1 : 63;
                stage8h(Vb + (size_t)(kt0 + jn) * 8 * 1024,
                        smb + (unsigned)(p ? VBA : VBB) * 4u, tc);
                CP_COMMIT();
            }

            float* SSc = sm + SSB + p * 2192;
            // ---- softmax over 16 heads (overlaps V(j) arrival) ----
            {
                float* pp = SSc + sxq * 137 + sxk * 17 + 8 * half;
                float e0 = __expf(pp[0]), e1 = __expf(pp[1]);
                float e2 = __expf(pp[2]), e3 = __expf(pp[3]);
                float e4 = __expf(pp[4]), e5 = __expf(pp[5]);
                float e6 = __expf(pp[6]), e7 = __expf(pp[7]);
                float s = ((e0 + e1) + (e2 + e3)) + ((e4 + e5) + (e6 + e7));
                s += __shfl_xor_sync(0xffffffffu, s, 1);
                const float inv = __frcp_rn(s);
                pp[0] = e0 * inv; pp[1] = e1 * inv; pp[2] = e2 * inv; pp[3] = e3 * inv;
                pp[4] = e4 * inv; pp[5] = e5 * inv; pp[6] = e6 * inv; pp[7] = e7 * inv;
            }

            CP_WAIT(1);            // V(j) arrived (thread-local)
            BARS(6, 256);          // V + softmax visible across consumers

            // ---- context for 2 heads ----
            const float* vbase = sm + (p ? VBB : VBA);
#pragma unroll
            for (int i = 0; i < 2; i++) {
                const int head = 2 * wc + i;
                unsigned a0 = f2tf(SSc[g * 137 + tig * 17 + head]);
                unsigned a1 = f2tf(SSc[(g + 8) * 137 + tig * 17 + head]);
                unsigned a2 = f2tf(SSc[g * 137 + (tig + 4) * 17 + head]);
                unsigned a3 = f2tf(SSc[(g + 8) * 137 + (tig + 4) * 17 + head]);
                const float* vlo = vbase + (head * 8 + tig) * 68;
                const float* vhi = vlo + 4 * 68;
#pragma unroll
                for (int nt = 0; nt < 8; nt++) {
                    unsigned b0 = ldu(vlo + nt * 8 + g);
                    unsigned b1 = ldu(vhi + nt * 8 + g);
                    mma_tf32(cacc[i][nt][0], cacc[i][nt][1], cacc[i][nt][2], cacc[i][nt][3],
                             a0, a1, a2, a3, b0, b1);
                }
            }
            if (j < 63) BARA(3 + p, 512);
        }

#pragma unroll
        for (int i = 0; i < 2; i++) {
            const int head = 2 * wc + i;
#pragma unroll
            for (int nt = 0; nt < 8; nt++) {
                const size_t base = ((size_t)b * 2048 + q0g + g) * 1024
                                  + head * 64 + nt * 8 + 2 * tig;
                atomicAdd(&Ctx[base + 0], cacc[i][nt][0]);
                atomicAdd(&Ctx[base + 1], cacc[i][nt][1]);
                atomicAdd(&Ctx[base + 8 * 1024 + 0], cacc[i][nt][2]);
                atomicAdd(&Ctx[base + 8 * 1024 + 1], cacc[i][nt][3]);
            }
        }
    }
}

// ================= LayerNorm over last dim (1024) =================
__global__ __launch_bounds__(256)
void ln_kernel(const float* __restrict__ x, const float* __restrict__ gamma,
               const float* __restrict__ beta, float* __restrict__ out) {
    __shared__ float red[16];
    const int row = blockIdx.x, t = threadIdx.x;
    float4 v = ((const float4*)(x + (size_t)row * 1024))[t];
    float s = v.x + v.y + v.z + v.w;
    float q = v.x * v.x + v.y * v.y + v.z * v.z + v.w * v.w;
#pragma unroll
    for (int o = 16; o > 0; o >>= 1) {
        s += __shfl_xor_sync(0xffffffffu, s, o);
        q += __shfl_xor_sync(0xffffffffu, q, o);
    }
    if ((t & 31) == 0) { red[t >> 5] = s; red[8 + (t >> 5)] = q; }
    __syncthreads();
    if (t < 8) {
        s = red[t]; q = red[8 + t];
#pragma unroll
        for (int o = 4; o > 0; o >>= 1) {
            s += __shfl_xor_sync(0xffu, s, o);
            q += __shfl_xor_sync(0xffu, q, o);
        }
        if (t == 0) { red[0] = s; red[1] = q; }
    }
    __syncthreads();
    const float mu = red[0] * (1.f / 1024.f);
    const float var = red[1] * (1.f / 1024.f) - mu * mu;
    const float inv = rsqrtf(var + 1e-5f);
    float4 g = ((const float4*)gamma)[t];
    float4 bb = ((const float4*)beta)[t];
    float4 o;
    o.x = (v.x - mu) * inv * g.x + bb.x;
    o.y = (v.y - mu) * inv * g.y + bb.y;
    o.z = (v.z - mu) * inv * g.z + bb.z;
    o.w = (v.w - mu) * inv * g.w + bb.w;
    ((float4*)(out + (size_t)row * 1024))[t] = o;
}

// ================= launch =================
extern "C" void kernel_launch(void* const* d_in, const int* in_sizes, int n_in,
                              void* d_out, int out_size) {
    const float* inQ = (const float*)d_in[0];
    const float* inK = (const float*)d_in[1];
    const float* inV = (const float*)d_in[2];
    const float* WQ  = (const float*)d_in[3];
    const float* WK  = (const float*)d_in[4];
    const float* WV  = (const float*)d_in[5];
    const float* WO  = (const float*)d_in[6];
    const float* gam = (const float*)d_in[7];
    const float* bet = (const float*)d_in[8];
    float* out = (float*)d_out;

    float* base = nullptr;
    cudaGetSymbolAddress((void**)&base, g_scratch);
    float* Qb = base;
    float* Kb = base + BUF;
    float* Vb = base + 2 * BUF;
    float* Cx = base + 3 * BUF;
    float* Xb = base + 4 * BUF;

    cudaFuncSetAttribute(qkv_gemm, cudaFuncAttributeMaxDynamicSharedMemorySize, GSM_BYTES);
    cudaFuncSetAttribute(o_gemm, cudaFuncAttributeMaxDynamicSharedMemorySize, GSM_BYTES);

    qkv_gemm<<<dim3(8, 32, 3), 256, GSM_BYTES>>>(inQ, inK, inV, WQ, WK, WV, Qb, Kb, Vb);

    cudaMemsetAsync(Cx, 0, BUF * sizeof(float));

    cudaFuncSetAttribute(attn_kernel, cudaFuncAttributeMaxDynamicSharedMemorySize, SM_BYTES);
    attn_kernel<<<dim3(128, 2, 4), 512, SM_BYTES>>>(Qb, Kb, Vb, Cx);

    o_gemm<<<dim3(8, 32), 256, GSM_BYTES>>>(Cx, WO, inQ, Xb);
    ln_kernel<<<4096, 256>>>(Xb, gam, bet, out);
}